// round 1
// baseline (speedup 1.0000x reference)
#include <cuda_runtime.h>
#include <cuda_bf16.h>
#include <math.h>
#include <stdint.h>

// ---------------------------------------------------------------------------
// Problem constants (stGCL): N=30000 nodes, E=480000 edges,
// IN_X=3000, IN_R=2048, NH=256, OUT=64.
// ---------------------------------------------------------------------------
#define N_NODES  30000
#define E_EDGES  480000

// Scratch (device globals: allocation-free rule)
__device__ float g_Hx[N_NODES * 256];     // features @ W1x
__device__ float g_Hr[N_NODES * 256];     // im_features @ W1r
__device__ float g_T0[N_NODES * 512];     // orig concat(h1x,h1r)  -> later decode proj g
__device__ float g_T1[N_NODES * 512];     // rand concat           -> later decode proj g
__device__ float g_U [N_NODES * 512];     // h3 scratch (orig then rand)
__device__ float g_scal[N_NODES * 4];     // es/ed buffers
__device__ int   g_rowptr[N_NODES + 1];
__device__ int   g_cnt[N_NODES];          // counts, then cursor
__device__ int   g_srcs[E_EDGES];         // CSR column (src) indices

// ---------------------------------------------------------------------------
// SGEMM: C[M,N] = A[M,K] * B     (BT=false: B is [K,N];  BT=true: B is [N,K])
// 128x128 tile, BK=16, 256 threads, 8x8 per-thread microtile.
// ---------------------------------------------------------------------------
template <bool BT>
__global__ __launch_bounds__(256)
void sgemm_kernel(int M, int N, int K,
                  const float* __restrict__ A, int lda,
                  const float* __restrict__ B, int ldb,
                  float* __restrict__ C, int ldc)
{
    __shared__ float As[16][132];
    __shared__ float Bs[16][132];

    const int tid = threadIdx.x;
    const int tx  = tid & 15;   // -> n
    const int ty  = tid >> 4;   // -> m
    const int m0  = blockIdx.y * 128;
    const int n0  = blockIdx.x * 128;

    float acc[8][8];
#pragma unroll
    for (int i = 0; i < 8; i++)
#pragma unroll
        for (int j = 0; j < 8; j++) acc[i][j] = 0.f;

    for (int k0 = 0; k0 < K; k0 += 16) {
        // Load A tile (128x16), store transposed As[k][m]
#pragma unroll
        for (int i = 0; i < 8; i++) {
            int idx = tid + i * 256;
            int mi = idx >> 4;
            int ki = idx & 15;
            int gm = m0 + mi, gk = k0 + ki;
            float v = 0.f;
            if (gm < M && gk < K) v = A[(size_t)gm * lda + gk];
            As[ki][mi] = v;
        }
        // Load B tile (16x128) as Bs[k][n]
#pragma unroll
        for (int i = 0; i < 8; i++) {
            int idx = tid + i * 256;
            float v = 0.f;
            if (!BT) {
                int ki = idx >> 7;
                int ni = idx & 127;
                int gk = k0 + ki, gn = n0 + ni;
                if (gk < K && gn < N) v = B[(size_t)gk * ldb + gn];
                Bs[ki][ni] = v;
            } else {
                int ni = idx >> 4;
                int ki = idx & 15;
                int gn = n0 + ni, gk = k0 + ki;
                if (gn < N && gk < K) v = B[(size_t)gn * ldb + gk];
                Bs[ki][ni] = v;
            }
        }
        __syncthreads();

#pragma unroll
        for (int k = 0; k < 16; k++) {
            float a[8], b[8];
            const float4* Ap = reinterpret_cast<const float4*>(&As[k][ty * 8]);
            const float4* Bp = reinterpret_cast<const float4*>(&Bs[k][tx * 8]);
            float4 a0 = Ap[0], a1 = Ap[1];
            float4 b0 = Bp[0], b1 = Bp[1];
            a[0]=a0.x; a[1]=a0.y; a[2]=a0.z; a[3]=a0.w;
            a[4]=a1.x; a[5]=a1.y; a[6]=a1.z; a[7]=a1.w;
            b[0]=b0.x; b[1]=b0.y; b[2]=b0.z; b[3]=b0.w;
            b[4]=b1.x; b[5]=b1.y; b[6]=b1.z; b[7]=b1.w;
#pragma unroll
            for (int i = 0; i < 8; i++)
#pragma unroll
                for (int j = 0; j < 8; j++)
                    acc[i][j] += a[i] * b[j];
        }
        __syncthreads();
    }

#pragma unroll
    for (int i = 0; i < 8; i++) {
        int gm = m0 + ty * 8 + i;
        if (gm >= M) continue;
#pragma unroll
        for (int j = 0; j < 8; j++) {
            int gn = n0 + tx * 8 + j;
            if (gn < N) C[(size_t)gm * ldc + gn] = acc[i][j];
        }
    }
}

// ---------------------------------------------------------------------------
// CSR build
// ---------------------------------------------------------------------------
__global__ void hist_kernel(const int* __restrict__ dst, int* cnt, int E)
{
    int i = blockIdx.x * blockDim.x + threadIdx.x;
    if (i < E) atomicAdd(&cnt[dst[i]], 1);
}

__global__ void scan_kernel(const int* counts, int* rowptr, int* cursor, int N, int E)
{
    __shared__ int sm[1024];
    int tid = threadIdx.x;
    int ch  = (N + 1023) / 1024;
    int b   = tid * ch;
    int e   = min(b + ch, N);
    int s = 0;
    for (int i = b; i < e; i++) s += counts[i];
    sm[tid] = s;
    __syncthreads();
    for (int off = 1; off < 1024; off <<= 1) {
        int t = (tid >= off) ? sm[tid - off] : 0;
        __syncthreads();
        sm[tid] += t;
        __syncthreads();
    }
    int run = (tid == 0) ? 0 : sm[tid - 1];
    for (int i = b; i < e; i++) {
        int c = counts[i];      // read BEFORE cursor write (may alias)
        rowptr[i] = run;
        cursor[i] = run;
        run += c;
    }
    if (tid == 0) rowptr[N] = E;
}

__global__ void fill_kernel(const int* __restrict__ src, const int* __restrict__ dst,
                            int* cursor, int* __restrict__ srcs, int E)
{
    int i = blockIdx.x * blockDim.x + threadIdx.x;
    if (i < E) {
        int p = atomicAdd(&cursor[dst[i]], 1);
        srcs[p] = src[i];
    }
}

// ---------------------------------------------------------------------------
// Per-node attention scalars: es = H . a_src, ed = H . a_dst (warp per node)
// ---------------------------------------------------------------------------
template <int NH>
__global__ void dots_kernel(const float* __restrict__ H,
                            const float* __restrict__ a_src,
                            const float* __restrict__ a_dst,
                            float* __restrict__ es, float* __restrict__ ed, int N)
{
    int gw   = (blockIdx.x * blockDim.x + threadIdx.x) >> 5;
    int lane = threadIdx.x & 31;
    if (gw >= N) return;
    const float* h = H + (size_t)gw * NH;
    float ps = 0.f, pd = 0.f;
#pragma unroll
    for (int c = lane; c < NH; c += 32) {
        float v = h[c];
        ps += v * __ldg(&a_src[c]);
        pd += v * __ldg(&a_dst[c]);
    }
#pragma unroll
    for (int o = 16; o; o >>= 1) {
        ps += __shfl_xor_sync(0xffffffffu, ps, o);
        pd += __shfl_xor_sync(0xffffffffu, pd, o);
    }
    if (lane == 0) { es[gw] = ps; ed[gw] = pd; }
}

// ---------------------------------------------------------------------------
// Fused GAT aggregation: segment softmax over incoming edges + weighted sum
// + elu epilogue. Warp per destination node, CSR-by-dst, float4 gathers.
// perm != nullptr: node features are H[perm[i]] (permuted encode path).
// ---------------------------------------------------------------------------
template <int NH>
__global__ void gat_agg_kernel(const float* __restrict__ H,
                               const float* __restrict__ es,
                               const float* __restrict__ ed,
                               const int* __restrict__ rowptr,
                               const int* __restrict__ srcs,
                               const int* __restrict__ perm,
                               float* __restrict__ out, int out_ld, int out_off, int N)
{
    constexpr int R4 = NH / 128;  // float4 per lane
    int gw   = (blockIdx.x * blockDim.x + threadIdx.x) >> 5;
    int lane = threadIdx.x & 31;
    if (gw >= N) return;

    int beg = rowptr[gw], end = rowptr[gw + 1];
    int dsti = perm ? __ldg(&perm[gw]) : gw;
    float edd = __ldg(&ed[dsti]);

    // Pass 1: segment max of leaky_relu(es[src] + ed[dst])
    float m = -INFINITY;
    for (int j = beg + lane; j < end; j += 32) {
        int s  = __ldg(&srcs[j]);
        int si = perm ? __ldg(&perm[s]) : s;
        float e = __ldg(&es[si]) + edd;
        e = e > 0.f ? e : 0.2f * e;
        m = fmaxf(m, e);
    }
#pragma unroll
    for (int o = 16; o; o >>= 1) m = fmaxf(m, __shfl_xor_sync(0xffffffffu, m, o));
    if (!isfinite(m)) m = 0.f;

    // Pass 2: accumulate exp(e-m) * h[src]; normalize at end
    float4 acc[R4];
#pragma unroll
    for (int c = 0; c < R4; c++) acc[c] = make_float4(0.f, 0.f, 0.f, 0.f);
    float sumw = 0.f;

    for (int j = beg; j < end; ++j) {
        int s  = __ldg(&srcs[j]);
        int si = perm ? __ldg(&perm[s]) : s;
        float e = __ldg(&es[si]) + edd;
        e = e > 0.f ? e : 0.2f * e;
        float w = expf(e - m);
        sumw += w;
        const float4* h4 = reinterpret_cast<const float4*>(H + (size_t)si * NH) + lane;
#pragma unroll
        for (int c = 0; c < R4; c++) {
            float4 v = __ldg(&h4[c * 32]);
            acc[c].x += w * v.x; acc[c].y += w * v.y;
            acc[c].z += w * v.z; acc[c].w += w * v.w;
        }
    }

    float inv = 1.f / (sumw + 1e-16f);
    float4* o4 = reinterpret_cast<float4*>(out + (size_t)gw * out_ld + out_off) + lane;
#pragma unroll
    for (int c = 0; c < R4; c++) {
        float4 v;
        v.x = acc[c].x * inv; v.y = acc[c].y * inv;
        v.z = acc[c].z * inv; v.w = acc[c].w * inv;
        v.x = v.x > 0.f ? v.x : expm1f(v.x);
        v.y = v.y > 0.f ? v.y : expm1f(v.y);
        v.z = v.z > 0.f ? v.z : expm1f(v.z);
        v.w = v.w > 0.f ? v.w : expm1f(v.w);
        o4[c * 32] = v;
    }
}

// ---------------------------------------------------------------------------
// summary = sigmoid(mean(h2, axis=0)); one block per column
// ---------------------------------------------------------------------------
__global__ void summary_kernel(const float* __restrict__ h2, float* __restrict__ out,
                               int N, int C)
{
    int c   = blockIdx.x;
    int tid = threadIdx.x;
    float s = 0.f;
    for (int r = tid; r < N; r += blockDim.x) s += h2[(size_t)r * C + c];
    __shared__ float sm[256];
    sm[tid] = s;
    __syncthreads();
    for (int o = 128; o; o >>= 1) {
        if (tid < o) sm[tid] += sm[tid + o];
        __syncthreads();
    }
    if (tid == 0) {
        float mval = sm[0] / (float)N;
        out[c] = 1.f / (1.f + expf(-mval));
    }
}

// ---------------------------------------------------------------------------
// Host orchestration
// ---------------------------------------------------------------------------
extern "C" void kernel_launch(void* const* d_in, const int* in_sizes, int n_in,
                              void* d_out, int out_size)
{
    const float* features    = (const float*)d_in[0];
    const float* im_features = (const float*)d_in[1];
    const float* W1x     = (const float*)d_in[2];
    const float* a1x_src = (const float*)d_in[3];
    const float* a1x_dst = (const float*)d_in[4];
    const float* W1r     = (const float*)d_in[5];
    const float* a1r_src = (const float*)d_in[6];
    const float* a1r_dst = (const float*)d_in[7];
    const float* W2      = (const float*)d_in[8];
    const float* a3_src  = (const float*)d_in[9];
    const float* a3_dst  = (const float*)d_in[10];
    const int*   ei      = (const int*)d_in[11];
    const int*   perm    = (const int*)d_in[12];

    const int N   = in_sizes[12];          // 30000
    const int E   = in_sizes[11] / 2;      // 480000
    const int NH  = in_sizes[3];           // 256
    const int INX = in_sizes[0] / N;       // 3000
    const int INR = in_sizes[1] / N;       // 2048
    const int OUT = in_sizes[8] / (2 * NH);// 64

    const int* srcI = ei;
    const int* dstI = ei + E;

    float *Hx, *Hr, *T0, *T1, *U, *scal;
    int *rp, *cnt, *sr;
    cudaGetSymbolAddress((void**)&Hx,  g_Hx);
    cudaGetSymbolAddress((void**)&Hr,  g_Hr);
    cudaGetSymbolAddress((void**)&T0,  g_T0);
    cudaGetSymbolAddress((void**)&T1,  g_T1);
    cudaGetSymbolAddress((void**)&U,   g_U);
    cudaGetSymbolAddress((void**)&scal,g_scal);
    cudaGetSymbolAddress((void**)&rp,  g_rowptr);
    cudaGetSymbolAddress((void**)&cnt, g_cnt);
    cudaGetSymbolAddress((void**)&sr,  g_srcs);

    float* out = (float*)d_out;
    size_t oH2   = 0;
    size_t oH4X  = oH2   + (size_t)N * OUT;
    size_t oH4R  = oH4X  + (size_t)N * INX;
    size_t oRH2  = oH4R  + (size_t)N * INR;
    size_t oRH4X = oRH2  + (size_t)N * OUT;
    size_t oRH4R = oRH4X + (size_t)N * INX;
    size_t oSUM  = oRH4R + (size_t)N * INR;

    auto gg = [](int M, int Nn) { return dim3((unsigned)((Nn + 127) / 128),
                                              (unsigned)((M + 127) / 128)); };
    const int WGRID = (N * 32 + 255) / 256;   // warp-per-node kernels

    // --- CSR by dst ---
    cudaMemsetAsync(cnt, 0, N * sizeof(int));
    hist_kernel<<<(E + 255) / 256, 256>>>(dstI, cnt, E);
    scan_kernel<<<1, 1024>>>(cnt, rp, cnt, N, E);
    fill_kernel<<<(E + 255) / 256, 256>>>(srcI, dstI, cnt, sr, E);

    // --- Forward projections (shared by orig & perm paths) ---
    sgemm_kernel<false><<<gg(N, NH), 256>>>(N, NH, INX, features,    INX, W1x, NH, Hx, NH);
    sgemm_kernel<false><<<gg(N, NH), 256>>>(N, NH, INR, im_features, INR, W1r, NH, Hr, NH);

    // --- Attention scalars ---
    dots_kernel<256><<<WGRID, 256>>>(Hx, a1x_src, a1x_dst, scal + 0 * N, scal + 1 * N, N);
    dots_kernel<256><<<WGRID, 256>>>(Hr, a1r_src, a1r_dst, scal + 2 * N, scal + 3 * N, N);

    // --- Encode aggregation (orig into T0, rand via perm into T1) ---
    gat_agg_kernel<256><<<WGRID, 256>>>(Hx, scal + 0 * N, scal + 1 * N, rp, sr, nullptr, T0, 512, 0,   N);
    gat_agg_kernel<256><<<WGRID, 256>>>(Hr, scal + 2 * N, scal + 3 * N, rp, sr, nullptr, T0, 512, 256, N);
    gat_agg_kernel<256><<<WGRID, 256>>>(Hx, scal + 0 * N, scal + 1 * N, rp, sr, perm,    T1, 512, 0,   N);
    gat_agg_kernel<256><<<WGRID, 256>>>(Hr, scal + 2 * N, scal + 3 * N, rp, sr, perm,    T1, 512, 256, N);

    // --- h2 = concat @ W2 ---
    sgemm_kernel<false><<<gg(N, OUT), 256>>>(N, OUT, 2 * NH, T0, 2 * NH, W2, OUT, out + oH2,  OUT);
    sgemm_kernel<false><<<gg(N, OUT), 256>>>(N, OUT, 2 * NH, T1, 2 * NH, W2, OUT, out + oRH2, OUT);

    summary_kernel<<<OUT, 256>>>(out + oH2, out + oSUM, N, OUT);

    // --- Decode: orig ---
    sgemm_kernel<true><<<gg(N, 2 * NH), 256>>>(N, 2 * NH, OUT, out + oH2, OUT, W2, OUT, T0, 2 * NH);
    dots_kernel<512><<<WGRID, 256>>>(T0, a3_src, a3_dst, scal + 0 * N, scal + 1 * N, N);
    gat_agg_kernel<512><<<WGRID, 256>>>(T0, scal + 0 * N, scal + 1 * N, rp, sr, nullptr, U, 512, 0, N);
    sgemm_kernel<true><<<gg(N, INX), 256>>>(N, INX, NH, U,       512, W1x, NH, out + oH4X, INX);
    sgemm_kernel<true><<<gg(N, INR), 256>>>(N, INR, NH, U + NH,  512, W1r, NH, out + oH4R, INR);

    // --- Decode: rand ---
    sgemm_kernel<true><<<gg(N, 2 * NH), 256>>>(N, 2 * NH, OUT, out + oRH2, OUT, W2, OUT, T1, 2 * NH);
    dots_kernel<512><<<WGRID, 256>>>(T1, a3_src, a3_dst, scal + 2 * N, scal + 3 * N, N);
    gat_agg_kernel<512><<<WGRID, 256>>>(T1, scal + 2 * N, scal + 3 * N, rp, sr, nullptr, U, 512, 0, N);
    sgemm_kernel<true><<<gg(N, INX), 256>>>(N, INX, NH, U,       512, W1x, NH, out + oRH4X, INX);
    sgemm_kernel<true><<<gg(N, INR), 256>>>(N, INR, NH, U + NH,  512, W1r, NH, out + oRH4R, INR);

    (void)n_in; (void)out_size;
}